// round 1
// baseline (speedup 1.0000x reference)
#include <cuda_runtime.h>
#include <mma.h>
#include <cstdint>
#include <cstddef>

using namespace nvcuda;

// ---------------------------------------------------------------------------
// Problem constants
// ---------------------------------------------------------------------------
static constexpr int D_MODEL = 1024;
static constexpr int N_HEAD  = 16;
static constexpr int N_KVH   = 4;
static constexpr int D_K     = 64;
static constexpr int Bb      = 2;
static constexpr int Ss      = 2048;
static constexpr int MTOT    = Bb * Ss;          // 4096
static constexpr int KV_D    = N_KVH * D_K;      // 256

// ---------------------------------------------------------------------------
// Scratch (no cudaMalloc allowed) : Q/K/V projections + attention output
// ---------------------------------------------------------------------------
__device__ float g_Q[(size_t)MTOT * D_MODEL];
__device__ float g_K[(size_t)MTOT * KV_D];
__device__ float g_V[(size_t)MTOT * KV_D];
__device__ float g_O[(size_t)MTOT * D_MODEL];

__device__ __forceinline__ float ex2f(float x) {
    float y;
    asm("ex2.approx.ftz.f32 %0, %1;" : "=f"(y) : "f"(x));
    return y;
}
__device__ __forceinline__ float to_tf32(float x) { return wmma::__float_to_tf32(x); }

// ---------------------------------------------------------------------------
// GEMM: C[M,N] = A[M,K] @ B[K,N], fp32 in/out, tf32 tensor-core compute.
// Block tile 128x64, K-step 32, 256 threads (8 warps -> 4x2 warp grid, each
// warp owns a 32x32 output tile as 2x2 m16n16k8 fragments).
// All dims here are multiples of the tiles (4096 x {1024,256} x 1024).
// ---------------------------------------------------------------------------
static constexpr int GBM = 128, GBN = 64, GBK = 32;
static constexpr int LDA_S = GBK + 4;   // 36 (mult of 4 floats)
static constexpr int LDB_S = GBN + 4;   // 68

__global__ __launch_bounds__(256) void gemm_tf32_kernel(
    const float* __restrict__ A, const float* __restrict__ Bm,
    float* __restrict__ C, int M, int N, int K)
{
    __shared__ __align__(32) float sA[GBM * LDA_S];
    __shared__ __align__(32) float sB[GBK * LDB_S];

    const int tid = threadIdx.x;
    const int wid = tid >> 5;
    const int wm  = wid >> 1;          // 0..3
    const int wn  = wid & 1;           // 0..1
    const int bm  = blockIdx.y * GBM;
    const int bn  = blockIdx.x * GBN;

    wmma::fragment<wmma::accumulator, 16, 16, 8, float> acc[2][2];
    #pragma unroll
    for (int i = 0; i < 2; i++)
        #pragma unroll
        for (int j = 0; j < 2; j++) wmma::fill_fragment(acc[i][j], 0.0f);

    const int ra = tid >> 3;           // 0..31
    const int ca = (tid & 7) * 4;      // 0..28
    const int rb = tid >> 4;           // 0..15
    const int cb = (tid & 15) * 4;     // 0..60

    for (int k0 = 0; k0 < K; k0 += GBK) {
        #pragma unroll
        for (int i = 0; i < 4; i++) {
            const float4 v = *(const float4*)&A[(size_t)(bm + ra + i * 32) * K + k0 + ca];
            float* p = &sA[(ra + i * 32) * LDA_S + ca];
            p[0] = to_tf32(v.x); p[1] = to_tf32(v.y);
            p[2] = to_tf32(v.z); p[3] = to_tf32(v.w);
        }
        #pragma unroll
        for (int i = 0; i < 2; i++) {
            const float4 v = *(const float4*)&Bm[(size_t)(k0 + rb + i * 16) * N + bn + cb];
            float* p = &sB[(rb + i * 16) * LDB_S + cb];
            p[0] = to_tf32(v.x); p[1] = to_tf32(v.y);
            p[2] = to_tf32(v.z); p[3] = to_tf32(v.w);
        }
        __syncthreads();

        #pragma unroll
        for (int kk = 0; kk < 4; kk++) {
            wmma::fragment<wmma::matrix_a, 16, 16, 8, wmma::precision::tf32, wmma::row_major> a0, a1;
            wmma::fragment<wmma::matrix_b, 16, 16, 8, wmma::precision::tf32, wmma::row_major> b0, b1;
            wmma::load_matrix_sync(a0, &sA[(wm * 32     ) * LDA_S + kk * 8], LDA_S);
            wmma::load_matrix_sync(a1, &sA[(wm * 32 + 16) * LDA_S + kk * 8], LDA_S);
            wmma::load_matrix_sync(b0, &sB[(kk * 8) * LDB_S + wn * 32     ], LDB_S);
            wmma::load_matrix_sync(b1, &sB[(kk * 8) * LDB_S + wn * 32 + 16], LDB_S);
            wmma::mma_sync(acc[0][0], a0, b0, acc[0][0]);
            wmma::mma_sync(acc[0][1], a0, b1, acc[0][1]);
            wmma::mma_sync(acc[1][0], a1, b0, acc[1][0]);
            wmma::mma_sync(acc[1][1], a1, b1, acc[1][1]);
        }
        __syncthreads();
    }

    #pragma unroll
    for (int i = 0; i < 2; i++)
        #pragma unroll
        for (int j = 0; j < 2; j++)
            wmma::store_matrix_sync(
                &C[(size_t)(bm + wm * 32 + i * 16) * N + bn + wn * 32 + j * 16],
                acc[i][j], N, wmma::mem_row_major);
}

// ---------------------------------------------------------------------------
// Flash attention (GQA): per CTA one (b,h, 128-row q-tile). d_k = 64.
// KV tiles of 64 rows, online softmax. tf32 wmma for QK^T and PV, all
// intermediate tiles staged in shared memory. log2(e)/sqrt(d_k) folded into
// Q so softmax is one ex2.approx per element.
// ---------------------------------------------------------------------------
static constexpr int QT  = 128;
static constexpr int KT  = 64;
static constexpr int LDS = 68;

static constexpr int SK_OFF = QT * LDS;            // after sQ
static constexpr int SV_OFF = SK_OFF + KT * LDS;
static constexpr int SS_OFF = SV_OFF + KT * LDS;
static constexpr int SO_OFF = SS_OFF + QT * LDS;
static constexpr int SM_OFF = SO_OFF + QT * LDS;
static constexpr int SL_OFF = SM_OFF + QT;
static constexpr int SMEM_FLOATS = SL_OFF + QT;    // 35072 floats
static constexpr int SMEM_BYTES  = SMEM_FLOATS * 4; // 140288 B

__global__ __launch_bounds__(256) void attn_kernel(
    const float* __restrict__ Qp, const float* __restrict__ Kp,
    const float* __restrict__ Vp, float* __restrict__ Op)
{
    extern __shared__ __align__(32) float sm[];
    float* sQ = sm;
    float* sK = sm + SK_OFF;
    float* sV = sm + SV_OFF;
    float* sS = sm + SS_OFF;
    float* sO = sm + SO_OFF;
    float* sMx = sm + SM_OFF;
    float* sL = sm + SL_OFF;

    const int tid = threadIdx.x;
    const int wid = tid >> 5;                   // 0..7, warp owns 16 q-rows
    const int bh  = blockIdx.y;
    const int b   = bh >> 4;
    const int h   = bh & 15;
    const int kvh = h >> 2;
    const int q0  = blockIdx.x * QT;

    const float qscale = 0.125f * 1.4426950408889634f;  // 1/sqrt(64) * log2(e)

    // ---- load + scale Q tile (128 x 64) ----
    {
        const int r  = tid >> 4;
        const int c4 = (tid & 15) * 4;
        #pragma unroll
        for (int i = 0; i < 8; i++) {
            const float4 v = *(const float4*)
                &Qp[(size_t)(b * Ss + q0 + r + i * 16) * D_MODEL + h * D_K + c4];
            float* p = &sQ[(r + i * 16) * LDS + c4];
            p[0] = to_tf32(v.x * qscale); p[1] = to_tf32(v.y * qscale);
            p[2] = to_tf32(v.z * qscale); p[3] = to_tf32(v.w * qscale);
        }
    }
    for (int i = tid; i < QT * D_K; i += 256) sO[(i >> 6) * LDS + (i & 63)] = 0.0f;
    if (tid < QT) { sMx[tid] = -1e30f; sL[tid] = 0.0f; }
    __syncthreads();

    for (int kt = 0; kt < Ss / KT; ++kt) {
        // ---- load K,V tiles (64 x 64 each) ----
        {
            const int r  = tid >> 4;
            const int c4 = (tid & 15) * 4;
            #pragma unroll
            for (int i = 0; i < 4; i++) {
                const size_t base =
                    (size_t)(b * Ss + kt * KT + r + i * 16) * KV_D + kvh * D_K + c4;
                const float4 kv = *(const float4*)&Kp[base];
                float* pk = &sK[(r + i * 16) * LDS + c4];
                pk[0] = to_tf32(kv.x); pk[1] = to_tf32(kv.y);
                pk[2] = to_tf32(kv.z); pk[3] = to_tf32(kv.w);
                const float4 vv = *(const float4*)&Vp[base];
                float* pv = &sV[(r + i * 16) * LDS + c4];
                pv[0] = to_tf32(vv.x); pv[1] = to_tf32(vv.y);
                pv[2] = to_tf32(vv.z); pv[3] = to_tf32(vv.w);
            }
        }
        __syncthreads();

        // ---- S = (Q*scale) @ K^T  (128x64 result; warp: 16 rows x 64 cols) ----
        {
            wmma::fragment<wmma::accumulator, 16, 16, 8, float> sf[4];
            #pragma unroll
            for (int j = 0; j < 4; j++) wmma::fill_fragment(sf[j], 0.0f);
            #pragma unroll
            for (int kk = 0; kk < 8; kk++) {
                wmma::fragment<wmma::matrix_a, 16, 16, 8, wmma::precision::tf32, wmma::row_major> a;
                wmma::load_matrix_sync(a, &sQ[(wid * 16) * LDS + kk * 8], LDS);
                #pragma unroll
                for (int j = 0; j < 4; j++) {
                    wmma::fragment<wmma::matrix_b, 16, 16, 8, wmma::precision::tf32, wmma::col_major> bf;
                    wmma::load_matrix_sync(bf, &sK[(j * 16) * LDS + kk * 8], LDS);
                    wmma::mma_sync(sf[j], a, bf, sf[j]);
                }
            }
            #pragma unroll
            for (int j = 0; j < 4; j++)
                wmma::store_matrix_sync(&sS[(wid * 16) * LDS + j * 16], sf[j],
                                        LDS, wmma::mem_row_major);
        }
        __syncthreads();

        // ---- online softmax (2 threads per row, 32 cols each) ----
        {
            const int r   = tid >> 1;
            const int off = (tid & 1) * 32;
            float* row = &sS[r * LDS + off];
            float mx = -1e30f;
            #pragma unroll
            for (int c = 0; c < 32; c++) mx = fmaxf(mx, row[c]);
            mx = fmaxf(mx, __shfl_xor_sync(0xffffffffu, mx, 1));
            const float mold = sMx[r];
            const float mnew = fmaxf(mold, mx);
            const float alpha = ex2f(mold - mnew);
            float sum = 0.0f;
            #pragma unroll
            for (int c = 0; c < 32; c++) {
                const float p = ex2f(row[c] - mnew);
                sum += p;
                row[c] = to_tf32(p);
            }
            sum += __shfl_xor_sync(0xffffffffu, sum, 1);
            if ((tid & 1) == 0) { sMx[r] = mnew; sL[r] = sL[r] * alpha + sum; }
            float* orow = &sO[r * LDS + off];
            #pragma unroll
            for (int c = 0; c < 32; c++) orow[c] *= alpha;
        }
        __syncthreads();

        // ---- O += P @ V ----
        {
            wmma::fragment<wmma::accumulator, 16, 16, 8, float> of[4];
            #pragma unroll
            for (int j = 0; j < 4; j++)
                wmma::load_matrix_sync(of[j], &sO[(wid * 16) * LDS + j * 16],
                                       LDS, wmma::mem_row_major);
            #pragma unroll
            for (int kk = 0; kk < 8; kk++) {
                wmma::fragment<wmma::matrix_a, 16, 16, 8, wmma::precision::tf32, wmma::row_major> a;
                wmma::load_matrix_sync(a, &sS[(wid * 16) * LDS + kk * 8], LDS);
                #pragma unroll
                for (int j = 0; j < 4; j++) {
                    wmma::fragment<wmma::matrix_b, 16, 16, 8, wmma::precision::tf32, wmma::row_major> bf;
                    wmma::load_matrix_sync(bf, &sV[(kk * 8) * LDS + j * 16], LDS);
                    wmma::mma_sync(of[j], a, bf, of[j]);
                }
            }
            #pragma unroll
            for (int j = 0; j < 4; j++)
                wmma::store_matrix_sync(&sO[(wid * 16) * LDS + j * 16], of[j],
                                        LDS, wmma::mem_row_major);
        }
        __syncthreads();
    }

    // ---- normalize and write out (layout (b, s, h, d) == (M, 1024)) ----
    {
        const int r   = tid >> 1;
        const int off = (tid & 1) * 32;
        const float inv = 1.0f / sL[r];
        const float* orow = &sO[r * LDS + off];
        float* dst = &Op[(size_t)(b * Ss + q0 + r) * D_MODEL + h * D_K + off];
        #pragma unroll
        for (int c = 0; c < 32; c += 4) {
            float4 v;
            v.x = orow[c + 0] * inv; v.y = orow[c + 1] * inv;
            v.z = orow[c + 2] * inv; v.w = orow[c + 3] * inv;
            *(float4*)&dst[c] = v;
        }
    }
}

// ---------------------------------------------------------------------------
// Launch
// ---------------------------------------------------------------------------
extern "C" void kernel_launch(void* const* d_in, const int* in_sizes, int n_in,
                              void* d_out, int out_size)
{
    const float* q  = (const float*)d_in[0];
    const float* k  = (const float*)d_in[1];
    const float* v  = (const float*)d_in[2];
    const float* Wq = (const float*)d_in[3];
    const float* Wk = (const float*)d_in[4];
    const float* Wv = (const float*)d_in[5];
    const float* Wo = (const float*)d_in[6];
    float* out = (float*)d_out;

    float *gq, *gk, *gv, *go;
    cudaGetSymbolAddress((void**)&gq, g_Q);
    cudaGetSymbolAddress((void**)&gk, g_K);
    cudaGetSymbolAddress((void**)&gv, g_V);
    cudaGetSymbolAddress((void**)&go, g_O);

    cudaFuncSetAttribute(attn_kernel,
                         cudaFuncAttributeMaxDynamicSharedMemorySize, SMEM_BYTES);

    // Q/K/V projections
    gemm_tf32_kernel<<<dim3(D_MODEL / GBN, MTOT / GBM), 256>>>(
        q, Wq, gq, MTOT, D_MODEL, D_MODEL);
    gemm_tf32_kernel<<<dim3(KV_D / GBN, MTOT / GBM), 256>>>(
        k, Wk, gk, MTOT, KV_D, D_MODEL);
    gemm_tf32_kernel<<<dim3(KV_D / GBN, MTOT / GBM), 256>>>(
        v, Wv, gv, MTOT, KV_D, D_MODEL);

    // Flash attention (GQA)
    attn_kernel<<<dim3(Ss / QT, Bb * N_HEAD), 256, SMEM_BYTES>>>(gq, gk, gv, go);

    // Output projection
    gemm_tf32_kernel<<<dim3(D_MODEL / GBN, MTOT / GBM), 256>>>(
        go, Wo, out, MTOT, D_MODEL, D_MODEL);
}

// round 3
// speedup vs baseline: 1.7780x; 1.7780x over previous
#include <cuda_runtime.h>
#include <mma.h>
#include <cstdint>
#include <cstddef>

using namespace nvcuda;

// ---------------------------------------------------------------------------
// Problem constants
// ---------------------------------------------------------------------------
static constexpr int D_MODEL = 1024;
static constexpr int N_HEAD  = 16;
static constexpr int N_KVH   = 4;
static constexpr int D_K     = 64;
static constexpr int Bb      = 2;
static constexpr int Ss      = 2048;
static constexpr int MTOT    = Bb * Ss;          // 4096
static constexpr int KV_D    = N_KVH * D_K;      // 256

// ---------------------------------------------------------------------------
// Scratch (no cudaMalloc allowed)
// ---------------------------------------------------------------------------
__device__ float g_Q[(size_t)MTOT * D_MODEL];
__device__ float g_K[(size_t)MTOT * KV_D];
__device__ float g_V[(size_t)MTOT * KV_D];
__device__ float g_O[(size_t)MTOT * D_MODEL];

__device__ __forceinline__ float ex2f(float x) {
    float y;
    asm("ex2.approx.ftz.f32 %0, %1;" : "=f"(y) : "f"(x));
    return y;
}
// tf32 round: destination must be a b32 register for ptxas
__device__ __forceinline__ float to_tf32(float x) {
    uint32_t y;
    asm("cvt.rna.tf32.f32 %0, %1;" : "=r"(y) : "f"(x));
    return __uint_as_float(y);
}

// mma.sync m16n8k8 tf32: D += A*B, A row-major 16x8, B col-major 8x8
__device__ __forceinline__ void mma_tf32(float c[4],
                                         uint32_t a0, uint32_t a1, uint32_t a2, uint32_t a3,
                                         uint32_t b0, uint32_t b1) {
    asm volatile(
        "mma.sync.aligned.m16n8k8.row.col.f32.tf32.tf32.f32 "
        "{%0,%1,%2,%3}, {%4,%5,%6,%7}, {%8,%9}, {%0,%1,%2,%3};\n"
        : "+f"(c[0]), "+f"(c[1]), "+f"(c[2]), "+f"(c[3])
        : "r"(a0), "r"(a1), "r"(a2), "r"(a3), "r"(b0), "r"(b1));
}

// ---------------------------------------------------------------------------
// GEMM: C[M,N] = A[M,K] @ B[K,N], fp32 in/out, tf32 wmma. (unchanged R1)
// ---------------------------------------------------------------------------
static constexpr int GBM = 128, GBN = 64, GBK = 32;
static constexpr int LDA_S = GBK + 4;
static constexpr int LDB_S = GBN + 4;

__global__ __launch_bounds__(256) void gemm_tf32_kernel(
    const float* __restrict__ A, const float* __restrict__ Bm,
    float* __restrict__ C, int M, int N, int K)
{
    __shared__ __align__(32) float sA[GBM * LDA_S];
    __shared__ __align__(32) float sB[GBK * LDB_S];

    const int tid = threadIdx.x;
    const int wid = tid >> 5;
    const int wm  = wid >> 1;
    const int wn  = wid & 1;
    const int bm  = blockIdx.y * GBM;
    const int bn  = blockIdx.x * GBN;

    wmma::fragment<wmma::accumulator, 16, 16, 8, float> acc[2][2];
    #pragma unroll
    for (int i = 0; i < 2; i++)
        #pragma unroll
        for (int j = 0; j < 2; j++) wmma::fill_fragment(acc[i][j], 0.0f);

    const int ra = tid >> 3;
    const int ca = (tid & 7) * 4;
    const int rb = tid >> 4;
    const int cb = (tid & 15) * 4;

    for (int k0 = 0; k0 < K; k0 += GBK) {
        #pragma unroll
        for (int i = 0; i < 4; i++) {
            const float4 v = *(const float4*)&A[(size_t)(bm + ra + i * 32) * K + k0 + ca];
            float* p = &sA[(ra + i * 32) * LDA_S + ca];
            p[0] = wmma::__float_to_tf32(v.x); p[1] = wmma::__float_to_tf32(v.y);
            p[2] = wmma::__float_to_tf32(v.z); p[3] = wmma::__float_to_tf32(v.w);
        }
        #pragma unroll
        for (int i = 0; i < 2; i++) {
            const float4 v = *(const float4*)&Bm[(size_t)(k0 + rb + i * 16) * N + bn + cb];
            float* p = &sB[(rb + i * 16) * LDB_S + cb];
            p[0] = wmma::__float_to_tf32(v.x); p[1] = wmma::__float_to_tf32(v.y);
            p[2] = wmma::__float_to_tf32(v.z); p[3] = wmma::__float_to_tf32(v.w);
        }
        __syncthreads();

        #pragma unroll
        for (int kk = 0; kk < 4; kk++) {
            wmma::fragment<wmma::matrix_a, 16, 16, 8, wmma::precision::tf32, wmma::row_major> a0, a1;
            wmma::fragment<wmma::matrix_b, 16, 16, 8, wmma::precision::tf32, wmma::row_major> b0, b1;
            wmma::load_matrix_sync(a0, &sA[(wm * 32     ) * LDA_S + kk * 8], LDA_S);
            wmma::load_matrix_sync(a1, &sA[(wm * 32 + 16) * LDA_S + kk * 8], LDA_S);
            wmma::load_matrix_sync(b0, &sB[(kk * 8) * LDB_S + wn * 32     ], LDB_S);
            wmma::load_matrix_sync(b1, &sB[(kk * 8) * LDB_S + wn * 32 + 16], LDB_S);
            wmma::mma_sync(acc[0][0], a0, b0, acc[0][0]);
            wmma::mma_sync(acc[0][1], a0, b1, acc[0][1]);
            wmma::mma_sync(acc[1][0], a1, b0, acc[1][0]);
            wmma::mma_sync(acc[1][1], a1, b1, acc[1][1]);
        }
        __syncthreads();
    }

    #pragma unroll
    for (int i = 0; i < 2; i++)
        #pragma unroll
        for (int j = 0; j < 2; j++)
            wmma::store_matrix_sync(
                &C[(size_t)(bm + wm * 32 + i * 16) * N + bn + wn * 32 + j * 16],
                acc[i][j], N, wmma::mem_row_major);
}

// ---------------------------------------------------------------------------
// Flash attention (GQA), registers-resident O + in-register softmax.
// CTA = 128 q-rows x (b,h); 8 warps, warp owns 16 rows. d_k = 64, KV tile 64.
// PTX mma m16n8k8 tf32. Per thread: rows g=lane>>2 and g+8 of its warp tile.
// ---------------------------------------------------------------------------
static constexpr int QT  = 128;
static constexpr int KT  = 64;
static constexpr int LDS = 68;

static constexpr int SQ_F = QT * LDS;
static constexpr int SK_F = KT * LDS;
static constexpr int SV_F = KT * LDS;
static constexpr int SP_F = QT * LDS;
static constexpr int SMEM_BYTES = (SQ_F + SK_F + SV_F + SP_F) * 4;  // 104448

__global__ __launch_bounds__(256, 2) void attn_kernel(
    const float* __restrict__ Qp, const float* __restrict__ Kp,
    const float* __restrict__ Vp, float* __restrict__ Op)
{
    extern __shared__ __align__(16) float sm[];
    float* sQ = sm;
    float* sK = sQ + SQ_F;
    float* sV = sK + SK_F;
    float* sP = sV + SV_F;
    const uint32_t* uQ = (const uint32_t*)sQ;
    const uint32_t* uK = (const uint32_t*)sK;
    const uint32_t* uV = (const uint32_t*)sV;
    const uint32_t* uP = (const uint32_t*)sP;

    const int tid  = threadIdx.x;
    const int wid  = tid >> 5;
    const int lane = tid & 31;
    const int g    = lane >> 2;       // row group 0..7
    const int t    = lane & 3;        // quad id 0..3
    const int wr   = wid * 16;        // warp's first q-row in tile

    const int bh  = blockIdx.y;
    const int b   = bh >> 4;
    const int h   = bh & 15;
    const int kvh = h >> 2;
    const int q0  = blockIdx.x * QT;

    const float qscale = 0.125f * 1.4426950408889634f;  // 1/sqrt(64)*log2(e)

    // ---- load + scale Q tile (128 x 64, tf32) ----
    {
        const int r  = tid >> 4;
        const int c4 = (tid & 15) * 4;
        #pragma unroll
        for (int i = 0; i < 8; i++) {
            const float4 v = *(const float4*)
                &Qp[(size_t)(b * Ss + q0 + r + i * 16) * D_MODEL + h * D_K + c4];
            float* p = &sQ[(r + i * 16) * LDS + c4];
            p[0] = to_tf32(v.x * qscale); p[1] = to_tf32(v.y * qscale);
            p[2] = to_tf32(v.z * qscale); p[3] = to_tf32(v.w * qscale);
        }
    }

    float Oacc[8][4];
    #pragma unroll
    for (int j = 0; j < 8; j++)
        #pragma unroll
        for (int i = 0; i < 4; i++) Oacc[j][i] = 0.0f;
    float m0 = -1e30f, m1 = -1e30f, l0 = 0.0f, l1 = 0.0f;

    for (int kt = 0; kt < Ss / KT; ++kt) {
        __syncthreads();   // previous iteration's readers of sK/sV are done
        // ---- load K,V tiles (64 x 64 each, tf32) ----
        {
            const int r  = tid >> 4;
            const int c4 = (tid & 15) * 4;
            #pragma unroll
            for (int i = 0; i < 4; i++) {
                const size_t base =
                    (size_t)(b * Ss + kt * KT + r + i * 16) * KV_D + kvh * D_K + c4;
                const float4 kv = *(const float4*)&Kp[base];
                float* pk = &sK[(r + i * 16) * LDS + c4];
                pk[0] = to_tf32(kv.x); pk[1] = to_tf32(kv.y);
                pk[2] = to_tf32(kv.z); pk[3] = to_tf32(kv.w);
                const float4 vv = *(const float4*)&Vp[base];
                float* pv = &sV[(r + i * 16) * LDS + c4];
                pv[0] = to_tf32(vv.x); pv[1] = to_tf32(vv.y);
                pv[2] = to_tf32(vv.z); pv[3] = to_tf32(vv.w);
            }
        }
        __syncthreads();

        // ---- S = Q @ K^T : warp computes 16 x 64, in registers ----
        float Sacc[8][4];
        #pragma unroll
        for (int j = 0; j < 8; j++)
            #pragma unroll
            for (int i = 0; i < 4; i++) Sacc[j][i] = 0.0f;

        #pragma unroll
        for (int kk = 0; kk < 8; kk++) {
            const uint32_t a0 = uQ[(wr + g    ) * LDS + kk * 8 + t    ];
            const uint32_t a1 = uQ[(wr + g + 8) * LDS + kk * 8 + t    ];
            const uint32_t a2 = uQ[(wr + g    ) * LDS + kk * 8 + t + 4];
            const uint32_t a3 = uQ[(wr + g + 8) * LDS + kk * 8 + t + 4];
            #pragma unroll
            for (int j = 0; j < 8; j++) {
                const uint32_t b0 = uK[(j * 8 + g) * LDS + kk * 8 + t    ];
                const uint32_t b1 = uK[(j * 8 + g) * LDS + kk * 8 + t + 4];
                mma_tf32(Sacc[j], a0, a1, a2, a3, b0, b1);
            }
        }

        // ---- online softmax in registers ----
        float mx0 = -1e30f, mx1 = -1e30f;
        #pragma unroll
        for (int j = 0; j < 8; j++) {
            mx0 = fmaxf(mx0, fmaxf(Sacc[j][0], Sacc[j][1]));
            mx1 = fmaxf(mx1, fmaxf(Sacc[j][2], Sacc[j][3]));
        }
        mx0 = fmaxf(mx0, __shfl_xor_sync(0xffffffffu, mx0, 1));
        mx0 = fmaxf(mx0, __shfl_xor_sync(0xffffffffu, mx0, 2));
        mx1 = fmaxf(mx1, __shfl_xor_sync(0xffffffffu, mx1, 1));
        mx1 = fmaxf(mx1, __shfl_xor_sync(0xffffffffu, mx1, 2));
        const float mn0 = fmaxf(m0, mx0);
        const float mn1 = fmaxf(m1, mx1);
        const float al0 = ex2f(m0 - mn0);
        const float al1 = ex2f(m1 - mn1);
        m0 = mn0; m1 = mn1;

        float s0 = 0.0f, s1 = 0.0f;
        float2* pr0 = (float2*)&sP[(wr + g    ) * LDS + t * 2];
        float2* pr1 = (float2*)&sP[(wr + g + 8) * LDS + t * 2];
        #pragma unroll
        for (int j = 0; j < 8; j++) {
            const float p00 = ex2f(Sacc[j][0] - mn0);
            const float p01 = ex2f(Sacc[j][1] - mn0);
            const float p10 = ex2f(Sacc[j][2] - mn1);
            const float p11 = ex2f(Sacc[j][3] - mn1);
            s0 += p00 + p01;
            s1 += p10 + p11;
            pr0[j * 4] = make_float2(to_tf32(p00), to_tf32(p01));
            pr1[j * 4] = make_float2(to_tf32(p10), to_tf32(p11));
        }
        s0 += __shfl_xor_sync(0xffffffffu, s0, 1);
        s0 += __shfl_xor_sync(0xffffffffu, s0, 2);
        s1 += __shfl_xor_sync(0xffffffffu, s1, 1);
        s1 += __shfl_xor_sync(0xffffffffu, s1, 2);
        l0 = l0 * al0 + s0;
        l1 = l1 * al1 + s1;

        #pragma unroll
        for (int j = 0; j < 8; j++) {
            Oacc[j][0] *= al0; Oacc[j][1] *= al0;
            Oacc[j][2] *= al1; Oacc[j][3] *= al1;
        }
        // sP rows are warp-private: no __syncthreads() needed before PV.

        // ---- O += P @ V ----
        #pragma unroll
        for (int kk = 0; kk < 8; kk++) {
            const uint32_t a0 = uP[(wr + g    ) * LDS + kk * 8 + t    ];
            const uint32_t a1 = uP[(wr + g + 8) * LDS + kk * 8 + t    ];
            const uint32_t a2 = uP[(wr + g    ) * LDS + kk * 8 + t + 4];
            const uint32_t a3 = uP[(wr + g + 8) * LDS + kk * 8 + t + 4];
            #pragma unroll
            for (int j = 0; j < 8; j++) {
                const uint32_t b0 = uV[(kk * 8 + t    ) * LDS + j * 8 + g];
                const uint32_t b1 = uV[(kk * 8 + t + 4) * LDS + j * 8 + g];
                mma_tf32(Oacc[j], a0, a1, a2, a3, b0, b1);
            }
        }
    }

    // ---- normalize + write out (layout (b, s, h, d) == (M, 1024)) ----
    const float inv0 = 1.0f / l0;
    const float inv1 = 1.0f / l1;
    float* d0 = &Op[(size_t)(b * Ss + q0 + wr + g    ) * D_MODEL + h * D_K + t * 2];
    float* d1 = &Op[(size_t)(b * Ss + q0 + wr + g + 8) * D_MODEL + h * D_K + t * 2];
    #pragma unroll
    for (int j = 0; j < 8; j++) {
        *(float2*)&d0[j * 8] = make_float2(Oacc[j][0] * inv0, Oacc[j][1] * inv0);
        *(float2*)&d1[j * 8] = make_float2(Oacc[j][2] * inv1, Oacc[j][3] * inv1);
    }
}

// ---------------------------------------------------------------------------
// Launch
// ---------------------------------------------------------------------------
extern "C" void kernel_launch(void* const* d_in, const int* in_sizes, int n_in,
                              void* d_out, int out_size)
{
    const float* q  = (const float*)d_in[0];
    const float* k  = (const float*)d_in[1];
    const float* v  = (const float*)d_in[2];
    const float* Wq = (const float*)d_in[3];
    const float* Wk = (const float*)d_in[4];
    const float* Wv = (const float*)d_in[5];
    const float* Wo = (const float*)d_in[6];
    float* out = (float*)d_out;

    float *gq, *gk, *gv, *go;
    cudaGetSymbolAddress((void**)&gq, g_Q);
    cudaGetSymbolAddress((void**)&gk, g_K);
    cudaGetSymbolAddress((void**)&gv, g_V);
    cudaGetSymbolAddress((void**)&go, g_O);

    cudaFuncSetAttribute(attn_kernel,
                         cudaFuncAttributeMaxDynamicSharedMemorySize, SMEM_BYTES);

    gemm_tf32_kernel<<<dim3(D_MODEL / GBN, MTOT / GBM), 256>>>(
        q, Wq, gq, MTOT, D_MODEL, D_MODEL);
    gemm_tf32_kernel<<<dim3(KV_D / GBN, MTOT / GBM), 256>>>(
        k, Wk, gk, MTOT, KV_D, D_MODEL);
    gemm_tf32_kernel<<<dim3(KV_D / GBN, MTOT / GBM), 256>>>(
        v, Wv, gv, MTOT, KV_D, D_MODEL);

    attn_kernel<<<dim3(Ss / QT, Bb * N_HEAD), 256, SMEM_BYTES>>>(gq, gk, gv, go);

    gemm_tf32_kernel<<<dim3(D_MODEL / GBN, MTOT / GBM), 256>>>(
        go, Wo, out, MTOT, D_MODEL, D_MODEL);
}